// round 9
// baseline (speedup 1.0000x reference)
#include <cuda_runtime.h>
#include <math.h>

// Problem constants
#define BB 4
#define LL 1024
#define DMODEL 512
#define DINNER 1024
#define DSTATE 16
#define DTRANK 32
#define DCONV 4
#define MM (BB * LL)              // 4096 rows for all GEMMs
#define NDBC (DTRANK + 2*DSTATE)  // 64

// ---------------------------------------------------------------------------
// Scratch buffers (static __device__ globals: allocation-free per harness rules)
// ---------------------------------------------------------------------------
__device__ float g_xz[MM * 2 * DINNER];   // [M, 2048]: cols 0..1023 = xc(raw), 1024..2047 = z
__device__ float g_xc[MM * DINNER];       // conv+silu output
__device__ float g_dbc[MM * NDBC];        // [M, 64]: dt 0..31, B 32..47, C 48..63
__device__ float g_delta[MM * DINNER];    // softplus(dt @ dt_proj^T + b)
__device__ float g_y[MM * DINNER];        // scan output, gated

// ---------------------------------------------------------------------------
// Tiled fp32 GEMM, NT layout: C[m,n] = sum_k A[m,k] * W[n,k]
// A row-major [M,lda>=K], W row-major [N,ldw>=K], C row-major [M,ldc>=N].
// EPI: 0 = none, 1 = add bias[n] then softplus.
// Double-buffered smem (1 sync / K-tile), +4-float row padding to cut STS
// bank conflicts while keeping 16B-aligned LDS.128 fragment reads.
// All instantiations divide exactly: no bounds checks.
// ---------------------------------------------------------------------------
template<int MT, int NT, int KC, int TM, int TN, int EPI, int THREADS>
__global__ void __launch_bounds__(THREADS, 2) gemm_nt(
    const float* __restrict__ A, const float* __restrict__ W,
    float* __restrict__ C, const float* __restrict__ bias,
    int K, int lda, int ldw, int ldc)
{
    constexpr int MP = MT + 4;            // padded row length (smem)
    constexpr int NP = NT + 4;
    __shared__ __align__(16) float As[2][KC][MP];
    __shared__ __align__(16) float Ws[2][KC][NP];

    const int tid = threadIdx.x;
    const int m0 = blockIdx.y * MT;
    const int n0 = blockIdx.x * NT;
    constexpr int NXT = NT / TN;          // threads along N
    const int tx = tid % NXT;
    const int ty = tid / NXT;
    const int row0 = ty * TM;
    const int col0 = tx * TN;

    constexpr int KC4 = KC / 4;
    constexpr int LA = (MT * KC4) / THREADS;   // float4 gmem loads per thread (A tile)
    constexpr int LW = (NT * KC4) / THREADS;
    static_assert(LA * THREADS == MT * KC4, "A tile load divisibility");
    static_assert(LW * THREADS == NT * KC4, "W tile load divisibility");
    static_assert((MT / TM) * (NT / TN) == THREADS, "thread tiling");

    float4 ra[LA], rw[LW];

    // ---- stage: gmem -> regs for K-chunk at k0 ----
    auto load_regs = [&](int k0) {
#pragma unroll
        for (int i = 0; i < LA; i++) {
            int idx = tid + i * THREADS;
            int r = idx / KC4, kq = idx % KC4;
            ra[i] = *(const float4*)(A + (size_t)(m0 + r) * lda + k0 + kq * 4);
        }
#pragma unroll
        for (int i = 0; i < LW; i++) {
            int idx = tid + i * THREADS;
            int r = idx / KC4, kq = idx % KC4;
            rw[i] = *(const float4*)(W + (size_t)(n0 + r) * ldw + k0 + kq * 4);
        }
    };
    // ---- stage: regs -> smem buffer `buf` (transposed to [k][m]) ----
    auto store_smem = [&](int buf) {
#pragma unroll
        for (int i = 0; i < LA; i++) {
            int idx = tid + i * THREADS;
            int r = idx / KC4, kq = idx % KC4;
            As[buf][kq*4+0][r] = ra[i].x; As[buf][kq*4+1][r] = ra[i].y;
            As[buf][kq*4+2][r] = ra[i].z; As[buf][kq*4+3][r] = ra[i].w;
        }
#pragma unroll
        for (int i = 0; i < LW; i++) {
            int idx = tid + i * THREADS;
            int r = idx / KC4, kq = idx % KC4;
            Ws[buf][kq*4+0][r] = rw[i].x; Ws[buf][kq*4+1][r] = rw[i].y;
            Ws[buf][kq*4+2][r] = rw[i].z; Ws[buf][kq*4+3][r] = rw[i].w;
        }
    };

    float acc[TM][TN];
#pragma unroll
    for (int i = 0; i < TM; i++)
#pragma unroll
        for (int j = 0; j < TN; j++) acc[i][j] = 0.f;

    const int KT = K / KC;
    load_regs(0);
    store_smem(0);
    __syncthreads();

    for (int kt = 0; kt < KT; kt++) {
        const int buf = kt & 1;
        if (kt + 1 < KT) load_regs((kt + 1) * KC);

#pragma unroll
        for (int kk = 0; kk < KC; kk++) {
            float a[TM], bfr[TN];
#pragma unroll
            for (int i = 0; i < TM; i += 4)
                *(float4*)(a + i) = *(const float4*)(&As[buf][kk][row0 + i]);
#pragma unroll
            for (int j = 0; j < TN; j += 4)
                *(float4*)(bfr + j) = *(const float4*)(&Ws[buf][kk][col0 + j]);
#pragma unroll
            for (int i = 0; i < TM; i++)
#pragma unroll
                for (int j = 0; j < TN; j++)
                    acc[i][j] = fmaf(a[i], bfr[j], acc[i][j]);
        }

        if (kt + 1 < KT) {
            store_smem((kt + 1) & 1);   // other buffer: safe (sync argument in header)
            __syncthreads();
        }
    }

#pragma unroll
    for (int i = 0; i < TM; i++) {
        int m = m0 + row0 + i;
#pragma unroll
        for (int j = 0; j < TN; j++) {
            int n = n0 + col0 + j;
            float v = acc[i][j];
            if (EPI == 1) {
                v += bias[n];
                v = (v > 20.f) ? v : log1pf(__expf(v));
            }
            C[(size_t)m * ldc + n] = v;
        }
    }
}

// ---------------------------------------------------------------------------
// Depthwise causal conv1d (taps l-3..l) + bias + SiLU.
// Input: g_xz cols 0..1023 (row stride 2048). Output: g_xc [M, 1024].
// ---------------------------------------------------------------------------
__global__ void conv_silu_kernel(const float* __restrict__ xz,
                                 const float* __restrict__ cw,
                                 const float* __restrict__ cb,
                                 float* __restrict__ out)
{
    int idx = blockIdx.x * blockDim.x + threadIdx.x;   // [0, MM*DINNER)
    int d = idx & (DINNER - 1);
    int m = idx >> 10;
    int l = m & (LL - 1);

    float4 wv = *(const float4*)(cw + d * 4);   // conv_w[d, 0, 0..3]
    const float* base = xz + (size_t)m * (2 * DINNER) + d;
    float acc = cb[d];
    if (l >= 3) acc = fmaf(wv.x, base[-3 * 2 * DINNER], acc);
    if (l >= 2) acc = fmaf(wv.y, base[-2 * 2 * DINNER], acc);
    if (l >= 1) acc = fmaf(wv.z, base[-1 * 2 * DINNER], acc);
    acc = fmaf(wv.w, base[0], acc);
    out[idx] = acc / (1.f + __expf(-acc));      // SiLU
}

// ---------------------------------------------------------------------------
// Selective scan. One state per lane: 16-lane group = one (b,d) chain,
// 2 channels per warp -> 2048 warps. Sequential over L; C-dot reduced via
// shfl within each 16-lane group. Fuses D*xc skip + SiLU(z) gate.
// ---------------------------------------------------------------------------
__global__ void scan_kernel(const float* __restrict__ delta,
                            const float* __restrict__ xc,
                            const float* __restrict__ dbc,
                            const float* __restrict__ xz,
                            const float* __restrict__ A_log,
                            const float* __restrict__ Dp,
                            float* __restrict__ y)
{
    int gtid = blockIdx.x * blockDim.x + threadIdx.x;
    int w = gtid >> 5;            // warp id, [0, 2048)
    int lane = gtid & 31;
    int s = lane & 15;            // state index
    int half = lane >> 4;         // which channel of the pair
    int b = w >> 9;               // 512 channel-pairs per batch
    int dpair = w & 511;
    int d = dpair * 2 + half;

    float Aval = -__expf(A_log[d * DSTATE + s]);
    float Dv = Dp[d];
    float h = 0.f;
    int mbase = b * LL;

    for (int l = 0; l < LL; l++) {
        int m = mbase + l;
        float dl = delta[m * DINNER + d];          // broadcast across 16 lanes
        float xv = xc[m * DINNER + d];             // broadcast
        float Bv = dbc[m * NDBC + DTRANK + s];
        float Cv = dbc[m * NDBC + DTRANK + DSTATE + s];

        float da = __expf(dl * Aval);
        h = fmaf(da, h, dl * Bv * xv);
        float p = h * Cv;
        p += __shfl_down_sync(0xffffffffu, p, 8, 16);
        p += __shfl_down_sync(0xffffffffu, p, 4, 16);
        p += __shfl_down_sync(0xffffffffu, p, 2, 16);
        p += __shfl_down_sync(0xffffffffu, p, 1, 16);
        if (s == 0) {
            float zv = xz[(size_t)m * (2 * DINNER) + DINNER + d];
            float yv = p + Dv * xv;
            y[m * DINNER + d] = yv * (zv / (1.f + __expf(-zv)));
        }
    }
}

// ---------------------------------------------------------------------------
// Launch
// ---------------------------------------------------------------------------
extern "C" void kernel_launch(void* const* d_in, const int* in_sizes, int n_in,
                              void* d_out, int out_size)
{
    const float* x          = (const float*)d_in[0];
    const float* in_proj_w  = (const float*)d_in[1];
    const float* conv_w     = (const float*)d_in[2];
    const float* conv_b     = (const float*)d_in[3];
    const float* x_proj_w   = (const float*)d_in[4];
    const float* dt_proj_w  = (const float*)d_in[5];
    const float* dt_proj_b  = (const float*)d_in[6];
    const float* A_log      = (const float*)d_in[7];
    const float* Dp         = (const float*)d_in[8];
    const float* out_proj_w = (const float*)d_in[9];
    float* out = (float*)d_out;

    float *xz, *xc, *dbc, *delta, *y;
    cudaGetSymbolAddress((void**)&xz,    g_xz);
    cudaGetSymbolAddress((void**)&xc,    g_xc);
    cudaGetSymbolAddress((void**)&dbc,   g_dbc);
    cudaGetSymbolAddress((void**)&delta, g_delta);
    cudaGetSymbolAddress((void**)&y,     g_y);

    // 1) in_proj: xz[M, 2048] = x[M,512] @ in_proj_w[2048,512]^T
    gemm_nt<128,128,16,8,8,0,256>
        <<<dim3((2*DINNER)/128, MM/128), 256>>>(x, in_proj_w, xz, nullptr,
                                                DMODEL, DMODEL, DMODEL, 2*DINNER);

    // 2) depthwise causal conv + SiLU -> xc[M,1024]
    conv_silu_kernel<<<(MM * DINNER) / 256, 256>>>(xz, conv_w, conv_b, xc);

    // 3) x_proj: dbc[M,64] = xc[M,1024] @ x_proj_w[64,1024]^T
    gemm_nt<32,64,32,4,4,0,128>
        <<<dim3(1, MM/32), 128>>>(xc, x_proj_w, dbc, nullptr,
                                  DINNER, DINNER, DINNER, NDBC);

    // 4) dt_proj + bias + softplus: delta[M,1024] = softplus(dt[M,32] @ dt_proj_w[1024,32]^T + b)
    gemm_nt<64,64,32,4,4,1,256>
        <<<dim3(DINNER/64, MM/64), 256>>>(dbc, dt_proj_w, delta, dt_proj_b,
                                          DTRANK, NDBC, DTRANK, DINNER);

    // 5) selective scan + skip + gate -> y[M,1024]
    scan_kernel<<<(BB * DINNER * 16) / 256, 256>>>(delta, xc, dbc, xz, A_log, Dp, y);

    // 6) out_proj: out[M,512] = y[M,1024] @ out_proj_w[512,1024]^T
    gemm_nt<128,128,16,8,8,0,256>
        <<<dim3(DMODEL/128, MM/128), 256>>>(y, out_proj_w, out, nullptr,
                                            DINNER, DINNER, DINNER, DMODEL);
}

// round 13
// speedup vs baseline: 1.0829x; 1.0829x over previous
#include <cuda_runtime.h>
#include <cuda_bf16.h>
#include <cstdint>
#include <math.h>

// Problem constants
#define BB 4
#define LL 1024
#define DMODEL 512
#define DINNER 1024
#define DSTATE 16
#define DTRANK 32
#define DCONV 4
#define MM (BB * LL)              // 4096 rows for all GEMMs
#define NDBC (DTRANK + 2*DSTATE)  // 64

// ---------------------------------------------------------------------------
// Scratch buffers (static __device__ globals: allocation-free per harness rules)
// ---------------------------------------------------------------------------
__device__ float g_xz[MM * 2 * DINNER];   // [M, 2048]: cols 0..1023 = xc(raw), 1024..2047 = z
__device__ float g_xc[MM * DINNER];       // conv+silu output
__device__ float g_dbc[MM * NDBC];        // [M, 64]: dt 0..31, B 32..47, C 48..63
__device__ float g_delta[MM * DINNER];    // softplus(dt @ dt_proj^T + b)

// bf16 hi/lo split buffers for tensor-core GEMMs (16B aligned for uint4 ldg)
__device__ __align__(16) __nv_bfloat16 g_xh[MM * DMODEL];
__device__ __align__(16) __nv_bfloat16 g_xl[MM * DMODEL];
__device__ __align__(16) __nv_bfloat16 g_wih[2 * DINNER * DMODEL];
__device__ __align__(16) __nv_bfloat16 g_wil[2 * DINNER * DMODEL];
__device__ __align__(16) __nv_bfloat16 g_yh[MM * DINNER];
__device__ __align__(16) __nv_bfloat16 g_yl[MM * DINNER];
__device__ __align__(16) __nv_bfloat16 g_woh[DMODEL * DINNER];
__device__ __align__(16) __nv_bfloat16 g_wol[DMODEL * DINNER];

// ---------------------------------------------------------------------------
// fp32 -> bf16 hi/lo split (hi = bf16(v); lo = bf16(v - hi))
// ---------------------------------------------------------------------------
__global__ void split_kernel(const float* __restrict__ in,
                             __nv_bfloat16* __restrict__ hi,
                             __nv_bfloat16* __restrict__ lo, int n)
{
    int i = blockIdx.x * blockDim.x + threadIdx.x;
    if (i < n) {
        float v = in[i];
        __nv_bfloat16 h = __float2bfloat16(v);
        hi[i] = h;
        lo[i] = __float2bfloat16(v - __bfloat162float(h));
    }
}

// ---------------------------------------------------------------------------
// bf16 split GEMM via mma.sync.m16n8k16 (NT: C[m,n] = sum_k A[m,k]*W[n,k]).
// A,W stored k-contiguous; fragments need no transpose. Computes
// Ah*Wh + Ah*Wl + Al*Wh (drops Al*Wl, ~2^-18 relative).
// Tile: BM=128, BN=64, BK=32; 8 warps (4x2), warp tile 32x32.
// Smem rows padded to 40 bf16 -> conflict-light 32-bit fragment loads.
// ---------------------------------------------------------------------------
__device__ __forceinline__ void mma_bf16(float* c, const unsigned* a, const unsigned* b)
{
    asm volatile(
        "mma.sync.aligned.m16n8k16.row.col.f32.bf16.bf16.f32 "
        "{%0,%1,%2,%3}, {%4,%5,%6,%7}, {%8,%9}, {%0,%1,%2,%3};\n"
        : "+f"(c[0]), "+f"(c[1]), "+f"(c[2]), "+f"(c[3])
        : "r"(a[0]), "r"(a[1]), "r"(a[2]), "r"(a[3]), "r"(b[0]), "r"(b[1]));
}

template<int KDIM>
__global__ void __launch_bounds__(256, 2) gemm_bf16_split(
    const __nv_bfloat16* __restrict__ Ah, const __nv_bfloat16* __restrict__ Al,
    const __nv_bfloat16* __restrict__ Wh, const __nv_bfloat16* __restrict__ Wl,
    float* __restrict__ C, int ldc)
{
    constexpr int BM = 128, BN = 64, BK = 32;
    constexpr int SA = BK + 8;                  // 40 bf16 row stride (80B)
    __shared__ __align__(16) __nv_bfloat16 sAh[BM * SA];
    __shared__ __align__(16) __nv_bfloat16 sAl[BM * SA];
    __shared__ __align__(16) __nv_bfloat16 sBh[BN * SA];
    __shared__ __align__(16) __nv_bfloat16 sBl[BN * SA];

    const int tid = threadIdx.x;
    const int wid = tid >> 5, lane = tid & 31;
    const int g = lane >> 2, t = lane & 3;      // mma group / thread-in-group
    const int wm = wid >> 1, wn = wid & 1;      // 4x2 warp grid
    const int m0 = blockIdx.y * BM;
    const int n0 = blockIdx.x * BN;
    const int wrow = wm * 32;
    const int wcol = wn * 32;

    float acc[2][4][4];
#pragma unroll
    for (int mt = 0; mt < 2; mt++)
#pragma unroll
        for (int nt = 0; nt < 4; nt++)
#pragma unroll
            for (int i = 0; i < 4; i++) acc[mt][nt][i] = 0.f;

    for (int k0 = 0; k0 < KDIM; k0 += BK) {
        // A tiles: 128 rows x 32 bf16 = 512 uint4 per tile, 2 per thread
#pragma unroll
        for (int it = 0; it < 2; it++) {
            int idx = tid + it * 256;
            int r = idx >> 2, q = idx & 3;
            const size_t src = (size_t)(m0 + r) * KDIM + k0 + q * 8;
            *(uint4*)&sAh[r * SA + q * 8] = *(const uint4*)&Ah[src];
            *(uint4*)&sAl[r * SA + q * 8] = *(const uint4*)&Al[src];
        }
        // B tiles: 64 rows x 32 bf16 = 256 uint4 per tile, 1 per thread
        {
            int r = tid >> 2, q = tid & 3;
            const size_t src = (size_t)(n0 + r) * KDIM + k0 + q * 8;
            *(uint4*)&sBh[r * SA + q * 8] = *(const uint4*)&Wh[src];
            *(uint4*)&sBl[r * SA + q * 8] = *(const uint4*)&Wl[src];
        }
        __syncthreads();

#pragma unroll
        for (int ks = 0; ks < BK; ks += 16) {
            unsigned ah[2][4], al[2][4], bh[4][2], bl[4][2];
#pragma unroll
            for (int mt = 0; mt < 2; mt++) {
                int r = wrow + mt * 16 + g;
                ah[mt][0] = *(const unsigned*)&sAh[r * SA + ks + 2 * t];
                ah[mt][1] = *(const unsigned*)&sAh[(r + 8) * SA + ks + 2 * t];
                ah[mt][2] = *(const unsigned*)&sAh[r * SA + ks + 8 + 2 * t];
                ah[mt][3] = *(const unsigned*)&sAh[(r + 8) * SA + ks + 8 + 2 * t];
                al[mt][0] = *(const unsigned*)&sAl[r * SA + ks + 2 * t];
                al[mt][1] = *(const unsigned*)&sAl[(r + 8) * SA + ks + 2 * t];
                al[mt][2] = *(const unsigned*)&sAl[r * SA + ks + 8 + 2 * t];
                al[mt][3] = *(const unsigned*)&sAl[(r + 8) * SA + ks + 8 + 2 * t];
            }
#pragma unroll
            for (int nt = 0; nt < 4; nt++) {
                int c = wcol + nt * 8 + g;
                bh[nt][0] = *(const unsigned*)&sBh[c * SA + ks + 2 * t];
                bh[nt][1] = *(const unsigned*)&sBh[c * SA + ks + 8 + 2 * t];
                bl[nt][0] = *(const unsigned*)&sBl[c * SA + ks + 2 * t];
                bl[nt][1] = *(const unsigned*)&sBl[c * SA + ks + 8 + 2 * t];
            }
#pragma unroll
            for (int mt = 0; mt < 2; mt++)
#pragma unroll
                for (int nt = 0; nt < 4; nt++) {
                    mma_bf16(acc[mt][nt], ah[mt], bh[nt]);   // hi*hi
                    mma_bf16(acc[mt][nt], ah[mt], bl[nt]);   // hi*lo
                    mma_bf16(acc[mt][nt], al[mt], bh[nt]);   // lo*hi
                }
        }
        __syncthreads();
    }

    // Epilogue: c0,c1 = (row g, cols 2t,2t+1); c2,c3 = (row g+8, same cols)
#pragma unroll
    for (int mt = 0; mt < 2; mt++) {
        int r0 = m0 + wrow + mt * 16 + g;
#pragma unroll
        for (int nt = 0; nt < 4; nt++) {
            int c0i = n0 + wcol + nt * 8 + 2 * t;
            *(float2*)&C[(size_t)r0 * ldc + c0i] =
                make_float2(acc[mt][nt][0], acc[mt][nt][1]);
            *(float2*)&C[(size_t)(r0 + 8) * ldc + c0i] =
                make_float2(acc[mt][nt][2], acc[mt][nt][3]);
        }
    }
}

// ---------------------------------------------------------------------------
// Tiled fp32 GEMM (used for x_proj and dt_proj), NT layout.
// EPI: 0 = none, 1 = add bias[n] then softplus.
// ---------------------------------------------------------------------------
template<int MT, int NT, int KC, int TM, int TN, int EPI, int THREADS>
__global__ void __launch_bounds__(THREADS, 2) gemm_nt(
    const float* __restrict__ A, const float* __restrict__ W,
    float* __restrict__ C, const float* __restrict__ bias,
    int K, int lda, int ldw, int ldc)
{
    constexpr int MP = MT + 4;
    constexpr int NP = NT + 4;
    __shared__ __align__(16) float As[2][KC][MP];
    __shared__ __align__(16) float Ws[2][KC][NP];

    const int tid = threadIdx.x;
    const int m0 = blockIdx.y * MT;
    const int n0 = blockIdx.x * NT;
    constexpr int NXT = NT / TN;
    const int tx = tid % NXT;
    const int ty = tid / NXT;
    const int row0 = ty * TM;
    const int col0 = tx * TN;

    constexpr int KC4 = KC / 4;
    constexpr int LA = (MT * KC4) / THREADS;
    constexpr int LW = (NT * KC4) / THREADS;
    static_assert(LA * THREADS == MT * KC4, "A tile load divisibility");
    static_assert(LW * THREADS == NT * KC4, "W tile load divisibility");
    static_assert((MT / TM) * (NT / TN) == THREADS, "thread tiling");

    float4 ra[LA], rw[LW];

    auto load_regs = [&](int k0) {
#pragma unroll
        for (int i = 0; i < LA; i++) {
            int idx = tid + i * THREADS;
            int r = idx / KC4, kq = idx % KC4;
            ra[i] = *(const float4*)(A + (size_t)(m0 + r) * lda + k0 + kq * 4);
        }
#pragma unroll
        for (int i = 0; i < LW; i++) {
            int idx = tid + i * THREADS;
            int r = idx / KC4, kq = idx % KC4;
            rw[i] = *(const float4*)(W + (size_t)(n0 + r) * ldw + k0 + kq * 4);
        }
    };
    auto store_smem = [&](int buf) {
#pragma unroll
        for (int i = 0; i < LA; i++) {
            int idx = tid + i * THREADS;
            int r = idx / KC4, kq = idx % KC4;
            As[buf][kq*4+0][r] = ra[i].x; As[buf][kq*4+1][r] = ra[i].y;
            As[buf][kq*4+2][r] = ra[i].z; As[buf][kq*4+3][r] = ra[i].w;
        }
#pragma unroll
        for (int i = 0; i < LW; i++) {
            int idx = tid + i * THREADS;
            int r = idx / KC4, kq = idx % KC4;
            Ws[buf][kq*4+0][r] = rw[i].x; Ws[buf][kq*4+1][r] = rw[i].y;
            Ws[buf][kq*4+2][r] = rw[i].z; Ws[buf][kq*4+3][r] = rw[i].w;
        }
    };

    float acc[TM][TN];
#pragma unroll
    for (int i = 0; i < TM; i++)
#pragma unroll
        for (int j = 0; j < TN; j++) acc[i][j] = 0.f;

    const int KT = K / KC;
    load_regs(0);
    store_smem(0);
    __syncthreads();

    for (int kt = 0; kt < KT; kt++) {
        const int buf = kt & 1;
        if (kt + 1 < KT) load_regs((kt + 1) * KC);

#pragma unroll
        for (int kk = 0; kk < KC; kk++) {
            float a[TM], bfr[TN];
#pragma unroll
            for (int i = 0; i < TM; i += 4)
                *(float4*)(a + i) = *(const float4*)(&As[buf][kk][row0 + i]);
#pragma unroll
            for (int j = 0; j < TN; j += 4)
                *(float4*)(bfr + j) = *(const float4*)(&Ws[buf][kk][col0 + j]);
#pragma unroll
            for (int i = 0; i < TM; i++)
#pragma unroll
                for (int j = 0; j < TN; j++)
                    acc[i][j] = fmaf(a[i], bfr[j], acc[i][j]);
        }

        if (kt + 1 < KT) {
            store_smem((kt + 1) & 1);
            __syncthreads();
        }
    }

#pragma unroll
    for (int i = 0; i < TM; i++) {
        int m = m0 + row0 + i;
#pragma unroll
        for (int j = 0; j < TN; j++) {
            int n = n0 + col0 + j;
            float v = acc[i][j];
            if (EPI == 1) {
                v += bias[n];
                v = (v > 20.f) ? v : log1pf(__expf(v));
            }
            C[(size_t)m * ldc + n] = v;
        }
    }
}

// ---------------------------------------------------------------------------
// Depthwise causal conv1d (taps l-3..l) + bias + SiLU.
// ---------------------------------------------------------------------------
__global__ void conv_silu_kernel(const float* __restrict__ xz,
                                 const float* __restrict__ cw,
                                 const float* __restrict__ cb,
                                 float* __restrict__ out)
{
    int idx = blockIdx.x * blockDim.x + threadIdx.x;
    int d = idx & (DINNER - 1);
    int m = idx >> 10;
    int l = m & (LL - 1);

    float4 wv = *(const float4*)(cw + d * 4);
    const float* base = xz + (size_t)m * (2 * DINNER) + d;
    float acc = cb[d];
    if (l >= 3) acc = fmaf(wv.x, base[-3 * 2 * DINNER], acc);
    if (l >= 2) acc = fmaf(wv.y, base[-2 * 2 * DINNER], acc);
    if (l >= 1) acc = fmaf(wv.z, base[-1 * 2 * DINNER], acc);
    acc = fmaf(wv.w, base[0], acc);
    out[idx] = acc / (1.f + __expf(-acc));
}

// ---------------------------------------------------------------------------
// Selective scan; emits y as bf16 hi/lo split so out_proj consumes directly.
// ---------------------------------------------------------------------------
__global__ void scan_kernel(const float* __restrict__ delta,
                            const float* __restrict__ xc,
                            const float* __restrict__ dbc,
                            const float* __restrict__ xz,
                            const float* __restrict__ A_log,
                            const float* __restrict__ Dp,
                            __nv_bfloat16* __restrict__ yh,
                            __nv_bfloat16* __restrict__ yl)
{
    int gtid = blockIdx.x * blockDim.x + threadIdx.x;
    int w = gtid >> 5;
    int lane = gtid & 31;
    int s = lane & 15;
    int half = lane >> 4;
    int b = w >> 9;
    int dpair = w & 511;
    int d = dpair * 2 + half;

    float Aval = -__expf(A_log[d * DSTATE + s]);
    float Dv = Dp[d];
    float h = 0.f;
    int mbase = b * LL;

    for (int l = 0; l < LL; l++) {
        int m = mbase + l;
        float dl = delta[m * DINNER + d];
        float xv = xc[m * DINNER + d];
        float Bv = dbc[m * NDBC + DTRANK + s];
        float Cv = dbc[m * NDBC + DTRANK + DSTATE + s];

        float da = __expf(dl * Aval);
        h = fmaf(da, h, dl * Bv * xv);
        float p = h * Cv;
        p += __shfl_down_sync(0xffffffffu, p, 8, 16);
        p += __shfl_down_sync(0xffffffffu, p, 4, 16);
        p += __shfl_down_sync(0xffffffffu, p, 2, 16);
        p += __shfl_down_sync(0xffffffffu, p, 1, 16);
        if (s == 0) {
            float zv = xz[(size_t)m * (2 * DINNER) + DINNER + d];
            float yv = (p + Dv * xv) * (zv / (1.f + __expf(-zv)));
            __nv_bfloat16 hi = __float2bfloat16(yv);
            yh[m * DINNER + d] = hi;
            yl[m * DINNER + d] = __float2bfloat16(yv - __bfloat162float(hi));
        }
    }
}

// ---------------------------------------------------------------------------
// Launch
// ---------------------------------------------------------------------------
extern "C" void kernel_launch(void* const* d_in, const int* in_sizes, int n_in,
                              void* d_out, int out_size)
{
    const float* x          = (const float*)d_in[0];
    const float* in_proj_w  = (const float*)d_in[1];
    const float* conv_w     = (const float*)d_in[2];
    const float* conv_b     = (const float*)d_in[3];
    const float* x_proj_w   = (const float*)d_in[4];
    const float* dt_proj_w  = (const float*)d_in[5];
    const float* dt_proj_b  = (const float*)d_in[6];
    const float* A_log      = (const float*)d_in[7];
    const float* Dp         = (const float*)d_in[8];
    const float* out_proj_w = (const float*)d_in[9];
    float* out = (float*)d_out;

    float *xz, *xc, *dbc, *delta;
    __nv_bfloat16 *xh, *xl, *wih, *wil, *yh, *yl, *woh, *wol;
    cudaGetSymbolAddress((void**)&xz,    g_xz);
    cudaGetSymbolAddress((void**)&xc,    g_xc);
    cudaGetSymbolAddress((void**)&dbc,   g_dbc);
    cudaGetSymbolAddress((void**)&delta, g_delta);
    cudaGetSymbolAddress((void**)&xh,    g_xh);
    cudaGetSymbolAddress((void**)&xl,    g_xl);
    cudaGetSymbolAddress((void**)&wih,   g_wih);
    cudaGetSymbolAddress((void**)&wil,   g_wil);
    cudaGetSymbolAddress((void**)&yh,    g_yh);
    cudaGetSymbolAddress((void**)&yl,    g_yl);
    cudaGetSymbolAddress((void**)&woh,   g_woh);
    cudaGetSymbolAddress((void**)&wol,   g_wol);

    // 0) bf16 hi/lo splits for in_proj operands
    split_kernel<<<(MM * DMODEL + 255) / 256, 256>>>(x, xh, xl, MM * DMODEL);
    split_kernel<<<(2 * DINNER * DMODEL + 255) / 256, 256>>>(in_proj_w, wih, wil,
                                                             2 * DINNER * DMODEL);

    // 1) in_proj (tensor cores): xz[M,2048] = x[M,512] @ in_proj_w[2048,512]^T
    gemm_bf16_split<DMODEL>
        <<<dim3((2 * DINNER) / 64, MM / 128), 256>>>(xh, xl, wih, wil, xz, 2 * DINNER);

    // 2) depthwise causal conv + SiLU -> xc[M,1024]
    conv_silu_kernel<<<(MM * DINNER) / 256, 256>>>(xz, conv_w, conv_b, xc);

    // 3) x_proj: dbc[M,64] = xc[M,1024] @ x_proj_w[64,1024]^T
    gemm_nt<32,64,32,4,4,0,128>
        <<<dim3(1, MM/32), 128>>>(xc, x_proj_w, dbc, nullptr,
                                  DINNER, DINNER, DINNER, NDBC);

    // 4) dt_proj + bias + softplus
    gemm_nt<64,64,32,4,4,1,256>
        <<<dim3(DINNER/64, MM/64), 256>>>(dbc, dt_proj_w, delta, dt_proj_b,
                                          DTRANK, NDBC, DTRANK, DINNER);

    // 5) selective scan + skip + gate -> y (bf16 hi/lo)
    scan_kernel<<<(BB * DINNER * 16) / 256, 256>>>(delta, xc, dbc, xz, A_log, Dp, yh, yl);

    // 5b) out_proj weight split
    split_kernel<<<(DMODEL * DINNER + 255) / 256, 256>>>(out_proj_w, woh, wol,
                                                         DMODEL * DINNER);

    // 6) out_proj (tensor cores): out[M,512] = y[M,1024] @ out_proj_w[512,1024]^T
    gemm_bf16_split<DINNER>
        <<<dim3(DMODEL / 64, MM / 128), 256>>>(yh, yl, woh, wol, out, DMODEL);
}

// round 15
// speedup vs baseline: 1.9514x; 1.8020x over previous
#include <cuda_runtime.h>
#include <cuda_bf16.h>
#include <cstdint>
#include <math.h>

// Problem constants
#define BB 4
#define LL 1024
#define DMODEL 512
#define DINNER 1024
#define DSTATE 16
#define DTRANK 32
#define DCONV 4
#define MM (BB * LL)              // 4096 rows for all GEMMs
#define NDBC (DTRANK + 2*DSTATE)  // 64
#define NC 8                      // scan chunks
#define CL (LL / NC)              // 128 timesteps per chunk

// ---------------------------------------------------------------------------
// Scratch buffers (static __device__ globals: allocation-free per harness rules)
// ---------------------------------------------------------------------------
__device__ float g_xz[MM * 2 * DINNER];   // [M, 2048]: cols 0..1023 = xc(raw), 1024..2047 = z
__device__ float g_xc[MM * DINNER];       // conv+silu output
__device__ float g_dbc[MM * NDBC];        // [M, 64]: dt 0..31, B 32..47, C 48..63
__device__ float g_delta[MM * DINNER];    // softplus(dt @ dt_proj^T + b)

// chunked-scan intermediates: [NC][BB][DINNER][16]
__device__ float g_hend [NC * BB * DINNER * DSTATE];
__device__ float g_aprod[NC * BB * DINNER * DSTATE];
__device__ float g_hinit[NC * BB * DINNER * DSTATE];

// bf16 hi/lo split buffers for tensor-core GEMMs (16B aligned for uint4 ldg)
__device__ __align__(16) __nv_bfloat16 g_xh[MM * DMODEL];
__device__ __align__(16) __nv_bfloat16 g_xl[MM * DMODEL];
__device__ __align__(16) __nv_bfloat16 g_wih[2 * DINNER * DMODEL];
__device__ __align__(16) __nv_bfloat16 g_wil[2 * DINNER * DMODEL];
__device__ __align__(16) __nv_bfloat16 g_yh[MM * DINNER];
__device__ __align__(16) __nv_bfloat16 g_yl[MM * DINNER];
__device__ __align__(16) __nv_bfloat16 g_woh[DMODEL * DINNER];
__device__ __align__(16) __nv_bfloat16 g_wol[DMODEL * DINNER];

// ---------------------------------------------------------------------------
// fp32 -> bf16 hi/lo split (hi = bf16(v); lo = bf16(v - hi))
// ---------------------------------------------------------------------------
__global__ void split_kernel(const float* __restrict__ in,
                             __nv_bfloat16* __restrict__ hi,
                             __nv_bfloat16* __restrict__ lo, int n)
{
    int i = blockIdx.x * blockDim.x + threadIdx.x;
    if (i < n) {
        float v = in[i];
        __nv_bfloat16 h = __float2bfloat16(v);
        hi[i] = h;
        lo[i] = __float2bfloat16(v - __bfloat162float(h));
    }
}

// ---------------------------------------------------------------------------
// bf16 split GEMM via mma.sync.m16n8k16 (NT: C[m,n] = sum_k A[m,k]*W[n,k]).
// Computes Ah*Wh + Ah*Wl + Al*Wh (drops Al*Wl, ~2^-18 relative).
// Tile: BM=128, BN=64, BK=32; 8 warps (4x2), warp tile 32x32.
// Reg-staged pipeline: gmem loads for tile k+1 issued before compute of k.
// ---------------------------------------------------------------------------
__device__ __forceinline__ void mma_bf16(float* c, const unsigned* a, const unsigned* b)
{
    asm volatile(
        "mma.sync.aligned.m16n8k16.row.col.f32.bf16.bf16.f32 "
        "{%0,%1,%2,%3}, {%4,%5,%6,%7}, {%8,%9}, {%0,%1,%2,%3};\n"
        : "+f"(c[0]), "+f"(c[1]), "+f"(c[2]), "+f"(c[3])
        : "r"(a[0]), "r"(a[1]), "r"(a[2]), "r"(a[3]), "r"(b[0]), "r"(b[1]));
}

template<int KDIM>
__global__ void __launch_bounds__(256, 2) gemm_bf16_split(
    const __nv_bfloat16* __restrict__ Ah, const __nv_bfloat16* __restrict__ Al,
    const __nv_bfloat16* __restrict__ Wh, const __nv_bfloat16* __restrict__ Wl,
    float* __restrict__ C, int ldc)
{
    constexpr int BM = 128, BN = 64, BK = 32;
    constexpr int SA = BK + 8;                  // 40 bf16 row stride (80B)
    __shared__ __align__(16) __nv_bfloat16 sAh[BM * SA];
    __shared__ __align__(16) __nv_bfloat16 sAl[BM * SA];
    __shared__ __align__(16) __nv_bfloat16 sBh[BN * SA];
    __shared__ __align__(16) __nv_bfloat16 sBl[BN * SA];

    const int tid = threadIdx.x;
    const int wid = tid >> 5, lane = tid & 31;
    const int g = lane >> 2, t = lane & 3;
    const int wm = wid >> 1, wn = wid & 1;
    const int m0 = blockIdx.y * BM;
    const int n0 = blockIdx.x * BN;
    const int wrow = wm * 32;
    const int wcol = wn * 32;

    // per-thread staging slots
    const int ra_r0 = tid >> 2,        ra_q = tid & 3;        // A row/quad (x2 via +256)
    const int ra_r1 = (tid + 256) >> 2;
    const int rb_r  = tid >> 2,        rb_q = tid & 3;        // B row/quad

    uint4 vAh0, vAl0, vAh1, vAl1, vBh, vBl;

    auto load_regs = [&](int k0) {
        size_t sa0 = (size_t)(m0 + ra_r0) * KDIM + k0 + ra_q * 8;
        size_t sa1 = (size_t)(m0 + ra_r1) * KDIM + k0 + ra_q * 8;
        size_t sb  = (size_t)(n0 + rb_r)  * KDIM + k0 + rb_q * 8;
        vAh0 = *(const uint4*)&Ah[sa0];  vAl0 = *(const uint4*)&Al[sa0];
        vAh1 = *(const uint4*)&Ah[sa1];  vAl1 = *(const uint4*)&Al[sa1];
        vBh  = *(const uint4*)&Wh[sb];   vBl  = *(const uint4*)&Wl[sb];
    };
    auto store_smem = [&]() {
        *(uint4*)&sAh[ra_r0 * SA + ra_q * 8] = vAh0;
        *(uint4*)&sAl[ra_r0 * SA + ra_q * 8] = vAl0;
        *(uint4*)&sAh[ra_r1 * SA + ra_q * 8] = vAh1;
        *(uint4*)&sAl[ra_r1 * SA + ra_q * 8] = vAl1;
        *(uint4*)&sBh[rb_r * SA + rb_q * 8]  = vBh;
        *(uint4*)&sBl[rb_r * SA + rb_q * 8]  = vBl;
    };

    float acc[2][4][4];
#pragma unroll
    for (int mt = 0; mt < 2; mt++)
#pragma unroll
        for (int nt = 0; nt < 4; nt++)
#pragma unroll
            for (int i = 0; i < 4; i++) acc[mt][nt][i] = 0.f;

    constexpr int KT = KDIM / BK;
    load_regs(0);
    store_smem();
    __syncthreads();

    for (int kt = 0; kt < KT; kt++) {
        if (kt + 1 < KT) load_regs((kt + 1) * BK);   // overlap with compute below

#pragma unroll
        for (int ks = 0; ks < BK; ks += 16) {
            unsigned ah[2][4], al[2][4], bh[4][2], bl[4][2];
#pragma unroll
            for (int mt = 0; mt < 2; mt++) {
                int r = wrow + mt * 16 + g;
                ah[mt][0] = *(const unsigned*)&sAh[r * SA + ks + 2 * t];
                ah[mt][1] = *(const unsigned*)&sAh[(r + 8) * SA + ks + 2 * t];
                ah[mt][2] = *(const unsigned*)&sAh[r * SA + ks + 8 + 2 * t];
                ah[mt][3] = *(const unsigned*)&sAh[(r + 8) * SA + ks + 8 + 2 * t];
                al[mt][0] = *(const unsigned*)&sAl[r * SA + ks + 2 * t];
                al[mt][1] = *(const unsigned*)&sAl[(r + 8) * SA + ks + 2 * t];
                al[mt][2] = *(const unsigned*)&sAl[r * SA + ks + 8 + 2 * t];
                al[mt][3] = *(const unsigned*)&sAl[(r + 8) * SA + ks + 8 + 2 * t];
            }
#pragma unroll
            for (int nt = 0; nt < 4; nt++) {
                int c = wcol + nt * 8 + g;
                bh[nt][0] = *(const unsigned*)&sBh[c * SA + ks + 2 * t];
                bh[nt][1] = *(const unsigned*)&sBh[c * SA + ks + 8 + 2 * t];
                bl[nt][0] = *(const unsigned*)&sBl[c * SA + ks + 2 * t];
                bl[nt][1] = *(const unsigned*)&sBl[c * SA + ks + 8 + 2 * t];
            }
#pragma unroll
            for (int mt = 0; mt < 2; mt++)
#pragma unroll
                for (int nt = 0; nt < 4; nt++) {
                    mma_bf16(acc[mt][nt], ah[mt], bh[nt]);   // hi*hi
                    mma_bf16(acc[mt][nt], ah[mt], bl[nt]);   // hi*lo
                    mma_bf16(acc[mt][nt], al[mt], bh[nt]);   // lo*hi
                }
        }

        if (kt + 1 < KT) {
            __syncthreads();          // all warps done reading this tile
            store_smem();             // overwrite with staged k+1 tile
            __syncthreads();          // tile visible to all
        }
    }

    // Epilogue: c0,c1 = (row g, cols 2t,2t+1); c2,c3 = (row g+8, same cols)
#pragma unroll
    for (int mt = 0; mt < 2; mt++) {
        int r0 = m0 + wrow + mt * 16 + g;
#pragma unroll
        for (int nt = 0; nt < 4; nt++) {
            int c0i = n0 + wcol + nt * 8 + 2 * t;
            *(float2*)&C[(size_t)r0 * ldc + c0i] =
                make_float2(acc[mt][nt][0], acc[mt][nt][1]);
            *(float2*)&C[(size_t)(r0 + 8) * ldc + c0i] =
                make_float2(acc[mt][nt][2], acc[mt][nt][3]);
        }
    }
}

// ---------------------------------------------------------------------------
// Tiled fp32 GEMM (used for x_proj and dt_proj), NT layout.
// EPI: 0 = none, 1 = add bias[n] then softplus.
// ---------------------------------------------------------------------------
template<int MT, int NT, int KC, int TM, int TN, int EPI, int THREADS>
__global__ void __launch_bounds__(THREADS, 2) gemm_nt(
    const float* __restrict__ A, const float* __restrict__ W,
    float* __restrict__ C, const float* __restrict__ bias,
    int K, int lda, int ldw, int ldc)
{
    constexpr int MP = MT + 4;
    constexpr int NP = NT + 4;
    __shared__ __align__(16) float As[2][KC][MP];
    __shared__ __align__(16) float Ws[2][KC][NP];

    const int tid = threadIdx.x;
    const int m0 = blockIdx.y * MT;
    const int n0 = blockIdx.x * NT;
    constexpr int NXT = NT / TN;
    const int tx = tid % NXT;
    const int ty = tid / NXT;
    const int row0 = ty * TM;
    const int col0 = tx * TN;

    constexpr int KC4 = KC / 4;
    constexpr int LA = (MT * KC4) / THREADS;
    constexpr int LW = (NT * KC4) / THREADS;
    static_assert(LA * THREADS == MT * KC4, "A tile load divisibility");
    static_assert(LW * THREADS == NT * KC4, "W tile load divisibility");
    static_assert((MT / TM) * (NT / TN) == THREADS, "thread tiling");

    float4 ra[LA], rw[LW];

    auto load_regs = [&](int k0) {
#pragma unroll
        for (int i = 0; i < LA; i++) {
            int idx = tid + i * THREADS;
            int r = idx / KC4, kq = idx % KC4;
            ra[i] = *(const float4*)(A + (size_t)(m0 + r) * lda + k0 + kq * 4);
        }
#pragma unroll
        for (int i = 0; i < LW; i++) {
            int idx = tid + i * THREADS;
            int r = idx / KC4, kq = idx % KC4;
            rw[i] = *(const float4*)(W + (size_t)(n0 + r) * ldw + k0 + kq * 4);
        }
    };
    auto store_smem = [&](int buf) {
#pragma unroll
        for (int i = 0; i < LA; i++) {
            int idx = tid + i * THREADS;
            int r = idx / KC4, kq = idx % KC4;
            As[buf][kq*4+0][r] = ra[i].x; As[buf][kq*4+1][r] = ra[i].y;
            As[buf][kq*4+2][r] = ra[i].z; As[buf][kq*4+3][r] = ra[i].w;
        }
#pragma unroll
        for (int i = 0; i < LW; i++) {
            int idx = tid + i * THREADS;
            int r = idx / KC4, kq = idx % KC4;
            Ws[buf][kq*4+0][r] = rw[i].x; Ws[buf][kq*4+1][r] = rw[i].y;
            Ws[buf][kq*4+2][r] = rw[i].z; Ws[buf][kq*4+3][r] = rw[i].w;
        }
    };

    float acc[TM][TN];
#pragma unroll
    for (int i = 0; i < TM; i++)
#pragma unroll
        for (int j = 0; j < TN; j++) acc[i][j] = 0.f;

    const int KT = K / KC;
    load_regs(0);
    store_smem(0);
    __syncthreads();

    for (int kt = 0; kt < KT; kt++) {
        const int buf = kt & 1;
        if (kt + 1 < KT) load_regs((kt + 1) * KC);

#pragma unroll
        for (int kk = 0; kk < KC; kk++) {
            float a[TM], bfr[TN];
#pragma unroll
            for (int i = 0; i < TM; i += 4)
                *(float4*)(a + i) = *(const float4*)(&As[buf][kk][row0 + i]);
#pragma unroll
            for (int j = 0; j < TN; j += 4)
                *(float4*)(bfr + j) = *(const float4*)(&Ws[buf][kk][col0 + j]);
#pragma unroll
            for (int i = 0; i < TM; i++)
#pragma unroll
                for (int j = 0; j < TN; j++)
                    acc[i][j] = fmaf(a[i], bfr[j], acc[i][j]);
        }

        if (kt + 1 < KT) {
            store_smem((kt + 1) & 1);
            __syncthreads();
        }
    }

#pragma unroll
    for (int i = 0; i < TM; i++) {
        int m = m0 + row0 + i;
#pragma unroll
        for (int j = 0; j < TN; j++) {
            int n = n0 + col0 + j;
            float v = acc[i][j];
            if (EPI == 1) {
                v += bias[n];
                v = (v > 20.f) ? v : log1pf(__expf(v));
            }
            C[(size_t)m * ldc + n] = v;
        }
    }
}

// ---------------------------------------------------------------------------
// Depthwise causal conv1d (taps l-3..l) + bias + SiLU.
// ---------------------------------------------------------------------------
__global__ void conv_silu_kernel(const float* __restrict__ xz,
                                 const float* __restrict__ cw,
                                 const float* __restrict__ cb,
                                 float* __restrict__ out)
{
    int idx = blockIdx.x * blockDim.x + threadIdx.x;
    int d = idx & (DINNER - 1);
    int m = idx >> 10;
    int l = m & (LL - 1);

    float4 wv = *(const float4*)(cw + d * 4);
    const float* base = xz + (size_t)m * (2 * DINNER) + d;
    float acc = cb[d];
    if (l >= 3) acc = fmaf(wv.x, base[-3 * 2 * DINNER], acc);
    if (l >= 2) acc = fmaf(wv.y, base[-2 * 2 * DINNER], acc);
    if (l >= 1) acc = fmaf(wv.z, base[-1 * 2 * DINNER], acc);
    acc = fmaf(wv.w, base[0], acc);
    out[idx] = acc / (1.f + __expf(-acc));
}

// ---------------------------------------------------------------------------
// Chunked selective scan, pass 1: per-chunk local scan from h=0.
// Warp layout: 16 lanes = 16 states of one (b,d) chain; 2 channels/warp.
// warp id w: [b:2][dpair:9][chunk:3]. Records h_end and prod(a) per state.
// No shfl, short dependency chain -> fast.
// ---------------------------------------------------------------------------
__global__ void scan_pass1(const float* __restrict__ delta,
                           const float* __restrict__ xc,
                           const float* __restrict__ dbc,
                           const float* __restrict__ A_log,
                           float* __restrict__ hend,
                           float* __restrict__ aprod)
{
    int gtid = blockIdx.x * blockDim.x + threadIdx.x;
    int w = gtid >> 5;
    int lane = gtid & 31;
    int s = lane & 15;
    int half = lane >> 4;
    int chunk = w & (NC - 1);
    int dpair = (w >> 3) & 511;
    int b = w >> 12;
    int d = dpair * 2 + half;

    float Aval = -__expf(A_log[d * DSTATE + s]);
    float h = 0.f, P = 1.f;
    int mbase = b * LL + chunk * CL;

    for (int l = 0; l < CL; l++) {
        int m = mbase + l;
        float dl = delta[m * DINNER + d];
        float xv = xc[m * DINNER + d];
        float Bv = dbc[m * NDBC + DTRANK + s];
        float da = __expf(dl * Aval);
        h = fmaf(da, h, dl * Bv * xv);
        P *= da;
    }
    size_t o = (((size_t)chunk * BB + b) * DINNER + d) * DSTATE + s;
    hend[o] = h;
    aprod[o] = P;
}

// ---------------------------------------------------------------------------
// Pass 2: sequential combine over NC chunks per (b,d,s).
// hinit[c] = state at START of chunk c (i.e. end of chunk c-1).
// ---------------------------------------------------------------------------
__global__ void scan_pass2(const float* __restrict__ hend,
                           const float* __restrict__ aprod,
                           float* __restrict__ hinit)
{
    int i = blockIdx.x * blockDim.x + threadIdx.x;   // [0, BB*DINNER*16)
    int b = i >> 14;                                  // DINNER*16 = 16384
    int rest = i & 16383;
    float H = 0.f;
#pragma unroll
    for (int c = 0; c < NC; c++) {
        size_t o = (((size_t)c * BB + b) << 14) + rest;
        hinit[o] = H;
        H = aprod[o] * H + hend[o];
    }
}

// ---------------------------------------------------------------------------
// Pass 3: re-run each chunk from its true h_init with C-dot + skip + gate;
// emits y as bf16 hi/lo split. Same warp layout as pass 1.
// ---------------------------------------------------------------------------
__global__ void scan_pass3(const float* __restrict__ delta,
                           const float* __restrict__ xc,
                           const float* __restrict__ dbc,
                           const float* __restrict__ xz,
                           const float* __restrict__ A_log,
                           const float* __restrict__ Dp,
                           const float* __restrict__ hinit,
                           __nv_bfloat16* __restrict__ yh,
                           __nv_bfloat16* __restrict__ yl)
{
    int gtid = blockIdx.x * blockDim.x + threadIdx.x;
    int w = gtid >> 5;
    int lane = gtid & 31;
    int s = lane & 15;
    int half = lane >> 4;
    int chunk = w & (NC - 1);
    int dpair = (w >> 3) & 511;
    int b = w >> 12;
    int d = dpair * 2 + half;

    float Aval = -__expf(A_log[d * DSTATE + s]);
    float Dv = Dp[d];
    float h = hinit[(((size_t)chunk * BB + b) * DINNER + d) * DSTATE + s];
    int mbase = b * LL + chunk * CL;

    for (int l = 0; l < CL; l++) {
        int m = mbase + l;
        float dl = delta[m * DINNER + d];
        float xv = xc[m * DINNER + d];
        float Bv = dbc[m * NDBC + DTRANK + s];
        float Cv = dbc[m * NDBC + DTRANK + DSTATE + s];

        float da = __expf(dl * Aval);
        h = fmaf(da, h, dl * Bv * xv);
        float p = h * Cv;
        p += __shfl_down_sync(0xffffffffu, p, 8, 16);
        p += __shfl_down_sync(0xffffffffu, p, 4, 16);
        p += __shfl_down_sync(0xffffffffu, p, 2, 16);
        p += __shfl_down_sync(0xffffffffu, p, 1, 16);
        if (s == 0) {
            float zv = xz[(size_t)m * (2 * DINNER) + DINNER + d];
            float yv = (p + Dv * xv) * (zv / (1.f + __expf(-zv)));
            __nv_bfloat16 hi = __float2bfloat16(yv);
            yh[m * DINNER + d] = hi;
            yl[m * DINNER + d] = __float2bfloat16(yv - __bfloat162float(hi));
        }
    }
}

// ---------------------------------------------------------------------------
// Launch
// ---------------------------------------------------------------------------
extern "C" void kernel_launch(void* const* d_in, const int* in_sizes, int n_in,
                              void* d_out, int out_size)
{
    const float* x          = (const float*)d_in[0];
    const float* in_proj_w  = (const float*)d_in[1];
    const float* conv_w     = (const float*)d_in[2];
    const float* conv_b     = (const float*)d_in[3];
    const float* x_proj_w   = (const float*)d_in[4];
    const float* dt_proj_w  = (const float*)d_in[5];
    const float* dt_proj_b  = (const float*)d_in[6];
    const float* A_log      = (const float*)d_in[7];
    const float* Dp         = (const float*)d_in[8];
    const float* out_proj_w = (const float*)d_in[9];
    float* out = (float*)d_out;

    float *xz, *xc, *dbc, *delta, *hend, *aprod, *hinit;
    __nv_bfloat16 *xh, *xl, *wih, *wil, *yh, *yl, *woh, *wol;
    cudaGetSymbolAddress((void**)&xz,    g_xz);
    cudaGetSymbolAddress((void**)&xc,    g_xc);
    cudaGetSymbolAddress((void**)&dbc,   g_dbc);
    cudaGetSymbolAddress((void**)&delta, g_delta);
    cudaGetSymbolAddress((void**)&hend,  g_hend);
    cudaGetSymbolAddress((void**)&aprod, g_aprod);
    cudaGetSymbolAddress((void**)&hinit, g_hinit);
    cudaGetSymbolAddress((void**)&xh,    g_xh);
    cudaGetSymbolAddress((void**)&xl,    g_xl);
    cudaGetSymbolAddress((void**)&wih,   g_wih);
    cudaGetSymbolAddress((void**)&wil,   g_wil);
    cudaGetSymbolAddress((void**)&yh,    g_yh);
    cudaGetSymbolAddress((void**)&yl,    g_yl);
    cudaGetSymbolAddress((void**)&woh,   g_woh);
    cudaGetSymbolAddress((void**)&wol,   g_wol);

    // 0) bf16 hi/lo splits for in_proj operands
    split_kernel<<<(MM * DMODEL + 255) / 256, 256>>>(x, xh, xl, MM * DMODEL);
    split_kernel<<<(2 * DINNER * DMODEL + 255) / 256, 256>>>(in_proj_w, wih, wil,
                                                             2 * DINNER * DMODEL);

    // 1) in_proj (tensor cores): xz[M,2048] = x[M,512] @ in_proj_w[2048,512]^T
    gemm_bf16_split<DMODEL>
        <<<dim3((2 * DINNER) / 64, MM / 128), 256>>>(xh, xl, wih, wil, xz, 2 * DINNER);

    // 2) depthwise causal conv + SiLU -> xc[M,1024]
    conv_silu_kernel<<<(MM * DINNER) / 256, 256>>>(xz, conv_w, conv_b, xc);

    // 3) x_proj: dbc[M,64] = xc[M,1024] @ x_proj_w[64,1024]^T
    gemm_nt<32,64,32,4,4,0,128>
        <<<dim3(1, MM/32), 128>>>(xc, x_proj_w, dbc, nullptr,
                                  DINNER, DINNER, DINNER, NDBC);

    // 4) dt_proj + bias + softplus
    gemm_nt<64,64,32,4,4,1,256>
        <<<dim3(DINNER/64, MM/64), 256>>>(dbc, dt_proj_w, delta, dt_proj_b,
                                          DTRANK, NDBC, DTRANK, DINNER);

    // 5) chunked selective scan (3 passes) -> y (bf16 hi/lo)
    scan_pass1<<<(BB * 512 * NC * 32) / 256, 256>>>(delta, xc, dbc, A_log, hend, aprod);
    scan_pass2<<<(BB * DINNER * DSTATE) / 256, 256>>>(hend, aprod, hinit);
    scan_pass3<<<(BB * 512 * NC * 32) / 256, 256>>>(delta, xc, dbc, xz, A_log, Dp,
                                                    hinit, yh, yl);

    // 5b) out_proj weight split
    split_kernel<<<(DMODEL * DINNER + 255) / 256, 256>>>(out_proj_w, woh, wol,
                                                         DMODEL * DINNER);

    // 6) out_proj (tensor cores): out[M,512] = y[M,1024] @ out_proj_w[512,1024]^T
    gemm_bf16_split<DINNER>
        <<<dim3(DMODEL / 64, MM / 128), 256>>>(yh, yl, woh, wol, out, DMODEL);
}